// round 12
// baseline (speedup 1.0000x reference)
#include <cuda_runtime.h>
#include <stdint.h>
#include <math.h>

#define BATCH 1024
#define DIM   128
#define N0    25
#define N1    10
#define NPB   250
#define FUSE_BLOCKS 32           // blocks 0..31 build g_Wf (8 product rows each)
#define FUSE_DONE FUSE_BLOCKS

// Fused weight: rows 0..127 = W0[0:128,:] ; rows 128..383 = W1 @ W0[128:256,:]
__device__ __align__(16) float g_Wf[384 * 128];
__device__ int g_flag;          // zero-init; monotonic across replays (benign: Wf replay-invariant)

// ---------------------------------------------------------------------------
// Single kernel. Blocks 0..31: fuse weights, release flag.
// Blocks 32..1055: gather+reduce ONE batch row (8 warps) -> smem act ->
// acquire flag -> matvec vs g_Wf (k split 2 ways) -> sigmoid -> out.
// 256 threads.
// ---------------------------------------------------------------------------
__global__ __launch_bounds__(256) void graphsage_kernel(
    const float* __restrict__ embed,
    const float* __restrict__ W0,
    const float* __restrict__ b0,
    const float* __restrict__ W1,
    const int*   __restrict__ roots,
    const int*   __restrict__ idx1,
    const int*   __restrict__ idx2,
    float*       __restrict__ out)
{
    const int tid = threadIdx.x;

    if (blockIdx.x < FUSE_BLOCKS) {
        // ------------------ fuse path (proven form) ------------------
        __shared__ __align__(16) float sW1[8 * 128];
        __shared__ __align__(16) float sRedF[2 * 8 * 128];

        const int fb  = blockIdx.x;
        const int kk0 = fb * 8;

        {   // copy W0a rows (4 rows per block)
            const int base = fb * 512;
#pragma unroll
            for (int i = 0; i < 2; i++)
                g_Wf[base + tid + i * 256] = __ldg(&W0[base + tid + i * 256]);
        }

        for (int i = tid; i < 1024; i += 256)
            sW1[i] = __ldg(&W1[kk0 * 128 + i]);
        __syncthreads();

        const int g = tid >> 7;
        const int d = tid & 127;

        float acc[8];
#pragma unroll
        for (int rr = 0; rr < 8; rr++) acc[rr] = 0.f;

        const int jbeg = g * 64;
        for (int j = 0; j < 64; j += 4) {
            float wv[4];
#pragma unroll
            for (int u = 0; u < 4; u++)
                wv[u] = __ldg(&W0[(size_t)(128 + jbeg + j + u) * 128 + d]);
#pragma unroll
            for (int u = 0; u < 4; u++) {
#pragma unroll
                for (int rr = 0; rr < 8; rr++)
                    acc[rr] = fmaf(sW1[rr * 128 + jbeg + j + u], wv[u], acc[rr]);
            }
        }

#pragma unroll
        for (int rr = 0; rr < 8; rr++)
            sRedF[g * 1024 + rr * 128 + d] = acc[rr];
        __syncthreads();

        if (g == 0) {
#pragma unroll
            for (int rr = 0; rr < 8; rr++)
                g_Wf[(size_t)(128 + kk0 + rr) * 128 + d] =
                    sRedF[rr * 128 + d] + sRedF[1024 + rr * 128 + d];
        }
        __threadfence();          // release
        __syncthreads();
        if (tid == 0) atomicAdd(&g_flag, 1);
        return;
    }

    // ------------------ gather (one batch row) + per-block MLP ------------------
    __shared__ int   sIdx2[NPB];
    __shared__ int   sIdx1[N0];
    __shared__ __align__(16) float sRedA[8 * 128];
    __shared__ __align__(16) float sRedB[8 * 128];
    __shared__ __align__(16) float sAct[384];
    __shared__ __align__(16) float sRedK[128];     // kg1 partial

    const int b = blockIdx.x - FUSE_BLOCKS;   // 0..1023

    const int w = tid >> 5;          // warp 0..7
    const int l = tid & 31;          // lane
    const int e = l * 4;             // float4 offset in 128-dim row

    if (tid < NPB) sIdx2[tid] = idx2[b * NPB + tid];
    if (tid < N0)  sIdx1[tid] = idx1[b * N0 + tid];
    __syncthreads();

    const float* E = embed + e;

    // leaf rows: warp w handles r = w, w+8, ... (4-deep proven unroll)
    float4 a2 = make_float4(0.f, 0.f, 0.f, 0.f);
    int r = w;
    for (; r + 24 < NPB; r += 32) {
        const float4 v0 = *(const float4*)(E + (size_t)sIdx2[r     ] * DIM);
        const float4 v1 = *(const float4*)(E + (size_t)sIdx2[r +  8] * DIM);
        const float4 v2 = *(const float4*)(E + (size_t)sIdx2[r + 16] * DIM);
        const float4 v3 = *(const float4*)(E + (size_t)sIdx2[r + 24] * DIM);
        a2.x += (v0.x + v1.x) + (v2.x + v3.x);
        a2.y += (v0.y + v1.y) + (v2.y + v3.y);
        a2.z += (v0.z + v1.z) + (v2.z + v3.z);
        a2.w += (v0.w + v1.w) + (v2.w + v3.w);
    }
    for (; r < NPB; r += 8) {
        const float4 v = *(const float4*)(E + (size_t)sIdx2[r] * DIM);
        a2.x += v.x; a2.y += v.y; a2.z += v.z; a2.w += v.w;
    }

    // idx1 rows
    float4 a1 = make_float4(0.f, 0.f, 0.f, 0.f);
    for (int q = w; q < N0; q += 8) {
        const float4 v = *(const float4*)(E + (size_t)sIdx1[q] * DIM);
        a1.x += v.x; a1.y += v.y; a1.z += v.z; a1.w += v.w;
    }

    // root embedding straight into sAct
    if (w == 0) {
        const float4 h0 = *(const float4*)(E + (size_t)__ldg(&roots[b]) * DIM);
        *(float4*)&sAct[e] = h0;
    }

    *(float4*)&sRedA[w * 128 + e] = a2;
    *(float4*)&sRedB[w * 128 + e] = a1;
    __syncthreads();

    // finish means
    if (tid < 128) {
        float s = 0.f;
#pragma unroll
        for (int j = 0; j < 8; j++) s += sRedB[j * 128 + tid];
        sAct[128 + tid] = s * (1.0f / 25.0f);
    } else {
        const int dd = tid - 128;
        float s = 0.f;
#pragma unroll
        for (int j = 0; j < 8; j++) s += sRedA[j * 128 + dd];
        sAct[256 + dd] = s * (1.0f / 250.0f);
    }

    // acquire fused weights (fuse blocks are wave-1; typically zero wait)
    if (tid == 0) {
        while (atomicAdd(&g_flag, 0) < FUSE_DONE) {}
        __threadfence();          // acquire
    }
    __syncthreads();

    // ------------------ per-block MLP: 1 row x 128 cols, k split 2 ways ----
    {
        const int d  = tid & 127;
        const int kg = tid >> 7;              // 0: k 0..191, 1: k 192..383
        const int kbeg = kg * 192;

        float acc = 0.f;
        for (int k0 = kbeg; k0 < kbeg + 192; k0 += 8) {
            float wv[8];
#pragma unroll
            for (int u = 0; u < 8; u++)
                wv[u] = __ldg(&g_Wf[(size_t)(k0 + u) * 128 + d]);
#pragma unroll
            for (int u = 0; u < 8; u++)
                acc = fmaf(sAct[k0 + u], wv[u], acc);
        }

        if (kg == 1) sRedK[d] = acc;
        __syncthreads();

        if (kg == 0) {
            const float x = acc + sRedK[d] + __ldg(&b0[d]);
            out[(size_t)b * 128 + d] = 1.0f / (1.0f + __expf(-x));
        }
    }
}

// ---------------------------------------------------------------------------
// Inputs: embed_table, W0, b0, W1, roots, idx1, idx2
// ---------------------------------------------------------------------------
extern "C" void kernel_launch(void* const* d_in, const int* in_sizes, int n_in,
                              void* d_out, int out_size)
{
    const float* embed = (const float*)d_in[0];
    const float* W0    = (const float*)d_in[1];
    const float* b0    = (const float*)d_in[2];
    const float* W1    = (const float*)d_in[3];
    const int*   roots = (const int*)  d_in[4];
    const int*   idx1  = (const int*)  d_in[5];
    const int*   idx2  = (const int*)  d_in[6];
    float*       out   = (float*)d_out;

    graphsage_kernel<<<FUSE_BLOCKS + BATCH, 256>>>(
        embed, W0, b0, W1, roots, idx1, idx2, out);
}

// round 13
// speedup vs baseline: 1.0536x; 1.0536x over previous
#include <cuda_runtime.h>
#include <stdint.h>
#include <math.h>

#define BATCH 1024
#define DIM   128
#define N0    25
#define N1    10
#define NPB   250
#define FUSE_BLOCKS 32           // blocks 0..31 build g_Wf (8 product rows each)
#define FUSE_DONE FUSE_BLOCKS

// Fused weight: rows 0..127 = W0[0:128,:] ; rows 128..383 = W1 @ W0[128:256,:]
__device__ __align__(16) float g_Wf[384 * 128];
__device__ int g_flag;          // zero-init; monotonic across replays (benign: Wf replay-invariant)

// ---------------------------------------------------------------------------
// Single kernel. Blocks 0..31: fuse weights, release flag.
// Blocks 32..1055: gather+reduce ONE batch row (8 warps) -> smem act ->
// acquire flag -> matvec vs g_Wf (float4 weights, 8-way k split) -> out.
// 256 threads.
// ---------------------------------------------------------------------------
__global__ __launch_bounds__(256) void graphsage_kernel(
    const float* __restrict__ embed,
    const float* __restrict__ W0,
    const float* __restrict__ b0,
    const float* __restrict__ W1,
    const int*   __restrict__ roots,
    const int*   __restrict__ idx1,
    const int*   __restrict__ idx2,
    float*       __restrict__ out)
{
    const int tid = threadIdx.x;

    if (blockIdx.x < FUSE_BLOCKS) {
        // ------------------ fuse path (proven form) ------------------
        __shared__ __align__(16) float sW1[8 * 128];
        __shared__ __align__(16) float sRedF[2 * 8 * 128];

        const int fb  = blockIdx.x;
        const int kk0 = fb * 8;

        {   // copy W0a rows (4 rows per block)
            const int base = fb * 512;
#pragma unroll
            for (int i = 0; i < 2; i++)
                g_Wf[base + tid + i * 256] = __ldg(&W0[base + tid + i * 256]);
        }

        for (int i = tid; i < 1024; i += 256)
            sW1[i] = __ldg(&W1[kk0 * 128 + i]);
        __syncthreads();

        const int g = tid >> 7;
        const int d = tid & 127;

        float acc[8];
#pragma unroll
        for (int rr = 0; rr < 8; rr++) acc[rr] = 0.f;

        const int jbeg = g * 64;
        for (int j = 0; j < 64; j += 4) {
            float wv[4];
#pragma unroll
            for (int u = 0; u < 4; u++)
                wv[u] = __ldg(&W0[(size_t)(128 + jbeg + j + u) * 128 + d]);
#pragma unroll
            for (int u = 0; u < 4; u++) {
#pragma unroll
                for (int rr = 0; rr < 8; rr++)
                    acc[rr] = fmaf(sW1[rr * 128 + jbeg + j + u], wv[u], acc[rr]);
            }
        }

#pragma unroll
        for (int rr = 0; rr < 8; rr++)
            sRedF[g * 1024 + rr * 128 + d] = acc[rr];
        __syncthreads();

        if (g == 0) {
#pragma unroll
            for (int rr = 0; rr < 8; rr++)
                g_Wf[(size_t)(128 + kk0 + rr) * 128 + d] =
                    sRedF[rr * 128 + d] + sRedF[1024 + rr * 128 + d];
        }
        __threadfence();          // release
        __syncthreads();
        if (tid == 0) atomicAdd(&g_flag, 1);
        return;
    }

    // ------------------ gather (one batch row) + per-block MLP ------------------
    __shared__ int   sIdx2[NPB];
    __shared__ int   sIdx1[N0];
    __shared__ __align__(16) float sRedA[8 * 128];
    __shared__ __align__(16) float sRedB[8 * 128];
    __shared__ __align__(16) float sAct[384];
    __shared__ __align__(16) float sRedM[8 * 128];   // kg partials [kg][col]

    const int b = blockIdx.x - FUSE_BLOCKS;   // 0..1023

    const int w = tid >> 5;          // warp 0..7
    const int l = tid & 31;          // lane
    const int e = l * 4;             // float4 offset in 128-dim row

    if (tid < NPB) sIdx2[tid] = idx2[b * NPB + tid];
    if (tid < N0)  sIdx1[tid] = idx1[b * N0 + tid];
    __syncthreads();

    const float* E = embed + e;

    // leaf rows: warp w handles r = w, w+8, ... (4-deep proven unroll)
    float4 a2 = make_float4(0.f, 0.f, 0.f, 0.f);
    int r = w;
    for (; r + 24 < NPB; r += 32) {
        const float4 v0 = *(const float4*)(E + (size_t)sIdx2[r     ] * DIM);
        const float4 v1 = *(const float4*)(E + (size_t)sIdx2[r +  8] * DIM);
        const float4 v2 = *(const float4*)(E + (size_t)sIdx2[r + 16] * DIM);
        const float4 v3 = *(const float4*)(E + (size_t)sIdx2[r + 24] * DIM);
        a2.x += (v0.x + v1.x) + (v2.x + v3.x);
        a2.y += (v0.y + v1.y) + (v2.y + v3.y);
        a2.z += (v0.z + v1.z) + (v2.z + v3.z);
        a2.w += (v0.w + v1.w) + (v2.w + v3.w);
    }
    for (; r < NPB; r += 8) {
        const float4 v = *(const float4*)(E + (size_t)sIdx2[r] * DIM);
        a2.x += v.x; a2.y += v.y; a2.z += v.z; a2.w += v.w;
    }

    // idx1 rows
    float4 a1 = make_float4(0.f, 0.f, 0.f, 0.f);
    for (int q = w; q < N0; q += 8) {
        const float4 v = *(const float4*)(E + (size_t)sIdx1[q] * DIM);
        a1.x += v.x; a1.y += v.y; a1.z += v.z; a1.w += v.w;
    }

    // root embedding straight into sAct
    if (w == 0) {
        const float4 h0 = *(const float4*)(E + (size_t)__ldg(&roots[b]) * DIM);
        *(float4*)&sAct[e] = h0;
    }

    *(float4*)&sRedA[w * 128 + e] = a2;
    *(float4*)&sRedB[w * 128 + e] = a1;
    __syncthreads();

    // finish means
    if (tid < 128) {
        float s = 0.f;
#pragma unroll
        for (int j = 0; j < 8; j++) s += sRedB[j * 128 + tid];
        sAct[128 + tid] = s * (1.0f / 25.0f);
    } else {
        const int dd = tid - 128;
        float s = 0.f;
#pragma unroll
        for (int j = 0; j < 8; j++) s += sRedA[j * 128 + dd];
        sAct[256 + dd] = s * (1.0f / 250.0f);
    }

    // acquire fused weights (fuse blocks are wave-1; typically zero wait)
    if (tid == 0) {
        while (atomicAdd(&g_flag, 0) < FUSE_DONE) {}
        __threadfence();          // acquire
    }
    __syncthreads();

    // ------------------ per-block MLP ------------------
    // thread = (cg = tid&31 -> 4 output cols, kg = tid>>5 -> 48 k's).
    // Per k: one LDG.128 of W[k][4cg..4cg+3] (512B/warp coalesced), broadcast
    // LDS of sAct[k], 4 FMA. 12288 LDG.128 per block vs 49152 LDG.32 before.
    {
        const int cg = tid & 31;
        const int kg = tid >> 5;
        const int kbeg = kg * 48;
        const float* Wp = g_Wf + (size_t)kbeg * 128 + cg * 4;

        float4 acc = make_float4(0.f, 0.f, 0.f, 0.f);
#pragma unroll 4
        for (int k = 0; k < 48; k++) {
            const float4 wv = *(const float4*)(Wp + (size_t)k * 128);
            const float a = sAct[kbeg + k];
            acc.x = fmaf(a, wv.x, acc.x);
            acc.y = fmaf(a, wv.y, acc.y);
            acc.z = fmaf(a, wv.z, acc.z);
            acc.w = fmaf(a, wv.w, acc.w);
        }
        *(float4*)&sRedM[kg * 128 + cg * 4] = acc;
    }
    __syncthreads();

    if (tid < 128) {
        float s = __ldg(&b0[tid]);
#pragma unroll
        for (int j = 0; j < 8; j++) s += sRedM[j * 128 + tid];
        out[(size_t)b * 128 + tid] = 1.0f / (1.0f + __expf(-s));
    }
}

// ---------------------------------------------------------------------------
// Inputs: embed_table, W0, b0, W1, roots, idx1, idx2
// ---------------------------------------------------------------------------
extern "C" void kernel_launch(void* const* d_in, const int* in_sizes, int n_in,
                              void* d_out, int out_size)
{
    const float* embed = (const float*)d_in[0];
    const float* W0    = (const float*)d_in[1];
    const float* b0    = (const float*)d_in[2];
    const float* W1    = (const float*)d_in[3];
    const int*   roots = (const int*)  d_in[4];
    const int*   idx1  = (const int*)  d_in[5];
    const int*   idx2  = (const int*)  d_in[6];
    float*       out   = (float*)d_out;

    graphsage_kernel<<<FUSE_BLOCKS + BATCH, 256>>>(
        embed, W0, b0, W1, roots, idx1, idx2, out);
}

// round 14
// speedup vs baseline: 1.0849x; 1.0298x over previous
#include <cuda_runtime.h>
#include <stdint.h>
#include <math.h>

#define BATCH 1024
#define DIM   128
#define N0    25
#define N1    10
#define NPB   250
#define FUSE_BLOCKS 32           // blocks 0..31 build g_Wf (8 product rows each)
#define FUSE_DONE FUSE_BLOCKS

// Fused weight: rows 0..127 = W0[0:128,:] ; rows 128..383 = W1 @ W0[128:256,:]
__device__ __align__(16) float g_Wf[384 * 128];
__device__ int g_flag;          // zero-init; monotonic across replays (benign: Wf replay-invariant)

// ---------------------------------------------------------------------------
// Single kernel. Blocks 0..31: fuse weights, release flag.
// Blocks 32..1055: software-pipelined gather of ONE batch row -> smem act ->
// acquire flag -> pipelined matvec vs g_Wf -> sigmoid -> out. 256 threads.
// ---------------------------------------------------------------------------
__global__ __launch_bounds__(256) void graphsage_kernel(
    const float* __restrict__ embed,
    const float* __restrict__ W0,
    const float* __restrict__ b0,
    const float* __restrict__ W1,
    const int*   __restrict__ roots,
    const int*   __restrict__ idx1,
    const int*   __restrict__ idx2,
    float*       __restrict__ out)
{
    const int tid = threadIdx.x;

    if (blockIdx.x < FUSE_BLOCKS) {
        // ------------------ fuse path (proven form) ------------------
        __shared__ __align__(16) float sW1[8 * 128];
        __shared__ __align__(16) float sRedF[2 * 8 * 128];

        const int fb  = blockIdx.x;
        const int kk0 = fb * 8;

        {   // copy W0a rows (4 rows per block)
            const int base = fb * 512;
#pragma unroll
            for (int i = 0; i < 2; i++)
                g_Wf[base + tid + i * 256] = __ldg(&W0[base + tid + i * 256]);
        }

        for (int i = tid; i < 1024; i += 256)
            sW1[i] = __ldg(&W1[kk0 * 128 + i]);
        __syncthreads();

        const int g = tid >> 7;
        const int d = tid & 127;

        float acc[8];
#pragma unroll
        for (int rr = 0; rr < 8; rr++) acc[rr] = 0.f;

        const int jbeg = g * 64;
        for (int j = 0; j < 64; j += 4) {
            float wv[4];
#pragma unroll
            for (int u = 0; u < 4; u++)
                wv[u] = __ldg(&W0[(size_t)(128 + jbeg + j + u) * 128 + d]);
#pragma unroll
            for (int u = 0; u < 4; u++) {
#pragma unroll
                for (int rr = 0; rr < 8; rr++)
                    acc[rr] = fmaf(sW1[rr * 128 + jbeg + j + u], wv[u], acc[rr]);
            }
        }

#pragma unroll
        for (int rr = 0; rr < 8; rr++)
            sRedF[g * 1024 + rr * 128 + d] = acc[rr];
        __syncthreads();

        if (g == 0) {
#pragma unroll
            for (int rr = 0; rr < 8; rr++)
                g_Wf[(size_t)(128 + kk0 + rr) * 128 + d] =
                    sRedF[rr * 128 + d] + sRedF[1024 + rr * 128 + d];
        }
        __threadfence();          // release
        __syncthreads();
        if (tid == 0) atomicAdd(&g_flag, 1);
        return;
    }

    // ------------------ gather (one batch row) + per-block MLP ------------------
    __shared__ int   sIdx2[NPB];
    __shared__ int   sIdx1[N0];
    __shared__ __align__(16) float sRedA[8 * 128];
    __shared__ __align__(16) float sRedB[8 * 128];
    __shared__ __align__(16) float sAct[384];
    __shared__ __align__(16) float sRedM[8 * 128];   // kg partials [kg][col]

    const int b = blockIdx.x - FUSE_BLOCKS;   // 0..1023

    const int w = tid >> 5;          // warp 0..7
    const int l = tid & 31;          // lane
    const int e = l * 4;             // float4 offset in 128-dim row

    if (tid < NPB) sIdx2[tid] = idx2[b * NPB + tid];
    if (tid < N0)  sIdx1[tid] = idx1[b * N0 + tid];
    __syncthreads();

    const float* E = embed + e;

    // ---- leaf rows: software-pipelined batches of 4 (load i+1, consume i) ----
    float4 a2 = make_float4(0.f, 0.f, 0.f, 0.f);
    float4 buf[4];
#pragma unroll
    for (int u = 0; u < 4; u++) {
        const int rr = w + u * 8;
        if (rr < NPB) buf[u] = *(const float4*)(E + (size_t)sIdx2[rr] * DIM);
        else          buf[u] = make_float4(0.f, 0.f, 0.f, 0.f);
    }
    for (int r = w + 32; r < NPB; r += 32) {
        float4 nxt[4];
#pragma unroll
        for (int u = 0; u < 4; u++) {
            const int rr = r + u * 8;
            if (rr < NPB) nxt[u] = *(const float4*)(E + (size_t)sIdx2[rr] * DIM);
            else          nxt[u] = make_float4(0.f, 0.f, 0.f, 0.f);
        }
#pragma unroll
        for (int u = 0; u < 4; u++) {
            a2.x += buf[u].x; a2.y += buf[u].y; a2.z += buf[u].z; a2.w += buf[u].w;
        }
#pragma unroll
        for (int u = 0; u < 4; u++) buf[u] = nxt[u];
    }
#pragma unroll
    for (int u = 0; u < 4; u++) {
        a2.x += buf[u].x; a2.y += buf[u].y; a2.z += buf[u].z; a2.w += buf[u].w;
    }

    // ---- idx1 rows (few per warp) ----
    float4 a1 = make_float4(0.f, 0.f, 0.f, 0.f);
    for (int q = w; q < N0; q += 8) {
        const float4 v = *(const float4*)(E + (size_t)sIdx1[q] * DIM);
        a1.x += v.x; a1.y += v.y; a1.z += v.z; a1.w += v.w;
    }

    // root embedding straight into sAct
    if (w == 0) {
        const float4 h0 = *(const float4*)(E + (size_t)__ldg(&roots[b]) * DIM);
        *(float4*)&sAct[e] = h0;
    }

    *(float4*)&sRedA[w * 128 + e] = a2;
    *(float4*)&sRedB[w * 128 + e] = a1;
    __syncthreads();

    // finish means
    if (tid < 128) {
        float s = 0.f;
#pragma unroll
        for (int j = 0; j < 8; j++) s += sRedB[j * 128 + tid];
        sAct[128 + tid] = s * (1.0f / 25.0f);
    } else {
        const int dd = tid - 128;
        float s = 0.f;
#pragma unroll
        for (int j = 0; j < 8; j++) s += sRedA[j * 128 + dd];
        sAct[256 + dd] = s * (1.0f / 250.0f);
    }

    // acquire fused weights (fuse blocks are wave-1; typically zero wait)
    if (tid == 0) {
        while (atomicAdd(&g_flag, 0) < FUSE_DONE) {}
        __threadfence();          // acquire
    }
    __syncthreads();

    // ------------------ per-block MLP (pipelined weight loads) ------------------
    // thread = (cg = tid&31 -> 4 output cols, kg = tid>>5 -> 48 k's).
    {
        const int cg = tid & 31;
        const int kg = tid >> 5;
        const int kbeg = kg * 48;
        const float* Wp = g_Wf + (size_t)kbeg * 128 + cg * 4;

        float4 acc = make_float4(0.f, 0.f, 0.f, 0.f);
        float4 wbuf[4];
#pragma unroll
        for (int u = 0; u < 4; u++)
            wbuf[u] = *(const float4*)(Wp + (size_t)u * 128);

        for (int k0 = 4; k0 < 48; k0 += 4) {
            float4 wn[4];
#pragma unroll
            for (int u = 0; u < 4; u++)
                wn[u] = *(const float4*)(Wp + (size_t)(k0 + u) * 128);
#pragma unroll
            for (int u = 0; u < 4; u++) {
                const float a = sAct[kbeg + k0 - 4 + u];
                acc.x = fmaf(a, wbuf[u].x, acc.x);
                acc.y = fmaf(a, wbuf[u].y, acc.y);
                acc.z = fmaf(a, wbuf[u].z, acc.z);
                acc.w = fmaf(a, wbuf[u].w, acc.w);
            }
#pragma unroll
            for (int u = 0; u < 4; u++) wbuf[u] = wn[u];
        }
#pragma unroll
        for (int u = 0; u < 4; u++) {
            const float a = sAct[kbeg + 44 + u];
            acc.x = fmaf(a, wbuf[u].x, acc.x);
            acc.y = fmaf(a, wbuf[u].y, acc.y);
            acc.z = fmaf(a, wbuf[u].z, acc.z);
            acc.w = fmaf(a, wbuf[u].w, acc.w);
        }

        *(float4*)&sRedM[kg * 128 + cg * 4] = acc;
    }
    __syncthreads();

    if (tid < 128) {
        float s = __ldg(&b0[tid]);
#pragma unroll
        for (int j = 0; j < 8; j++) s += sRedM[j * 128 + tid];
        out[(size_t)b * 128 + tid] = 1.0f / (1.0f + __expf(-s));
    }
}

// ---------------------------------------------------------------------------
// Inputs: embed_table, W0, b0, W1, roots, idx1, idx2
// ---------------------------------------------------------------------------
extern "C" void kernel_launch(void* const* d_in, const int* in_sizes, int n_in,
                              void* d_out, int out_size)
{
    const float* embed = (const float*)d_in[0];
    const float* W0    = (const float*)d_in[1];
    const float* b0    = (const float*)d_in[2];
    const float* W1    = (const float*)d_in[3];
    const int*   roots = (const int*)  d_in[4];
    const int*   idx1  = (const int*)  d_in[5];
    const int*   idx2  = (const int*)  d_in[6];
    float*       out   = (float*)d_out;

    graphsage_kernel<<<FUSE_BLOCKS + BATCH, 256>>>(
        embed, W0, b0, W1, roots, idx1, idx2, out);
}